// round 1
// baseline (speedup 1.0000x reference)
#include <cuda_runtime.h>
#include <math.h>

#define SEQ  40
#define H    4096
#define OUT  128
#define NBLK 256
#define NTHR 256
#define JPB  (H / NBLK)   // 16 hidden indices per block

// Persistent state (device globals: no allocation allowed)
__device__ float    g_h[2][H];          // ping-pong hidden state
__device__ unsigned g_bar_count = 0;    // self-resetting
__device__ unsigned g_bar_gen   = 0;    // monotonic generation

__device__ __forceinline__ void grid_barrier() {
    __syncthreads();
    if (threadIdx.x == 0) {
        unsigned gen = atomicAdd(&g_bar_gen, 0u);   // snapshot generation
        __threadfence();                            // publish my block's writes
        if (atomicAdd(&g_bar_count, 1u) == NBLK - 1u) {
            g_bar_count = 0;
            __threadfence();
            atomicAdd(&g_bar_gen, 1u);              // release
        } else {
            volatile unsigned* vg = &g_bar_gen;
            while (*vg == gen) { }
            __threadfence();                        // acquire
        }
    }
    __syncthreads();
}

__global__ __launch_bounds__(NTHR, 2)
void lstm_persistent_kernel(const float* __restrict__ x,
                            const float* __restrict__ w_ih,
                            const float* __restrict__ w_hh,
                            const float* __restrict__ b_ih,
                            const float* __restrict__ b_hh,
                            const float* __restrict__ dense_w,
                            const float* __restrict__ dense_b,
                            float* __restrict__ out) {
    __shared__ float4 h_s[H / 4];      // 16 KB staged h_{t-1}
    __shared__ float  gsm[4][JPB];     // per-gate dot results
    __shared__ float  c_s[JPB];        // persistent cell state for owned j's
    __shared__ float  red[NTHR / 32];  // dense epilogue reduction

    const int tid  = threadIdx.x;
    const int lane = tid & 31;
    const int wid  = tid >> 5;
    const int j0   = blockIdx.x * JPB;

    if (tid < JPB) c_s[tid] = 0.0f;    // c_0 = 0 (re-init every launch)

    for (int t = 0; t < SEQ; ++t) {
        if (t > 0) {
            // stage h_{t-1} into shared memory (coalesced float4)
            const float4* hb = (const float4*)g_h[(t - 1) & 1];
            #pragma unroll
            for (int k = 0; k < (H / 4) / NTHR; ++k)
                h_s[tid + k * NTHR] = hb[tid + k * NTHR];
            __syncthreads();

            // 64 rows per block (4 gates x 16 j). Warp w handles rows w*8..w*8+7.
            for (int rr = 0; rr < 8; ++rr) {
                const int rloc = wid * 8 + rr;        // 0..63, unique per (warp,rr)
                const int gate = rloc >> 4;           // 0:i 1:f 2:g 3:o
                const int jj   = rloc & 15;
                const float4* wrow =
                    (const float4*)(w_hh + (size_t)(gate * H + j0 + jj) * H);
                float acc = 0.0f;
                #pragma unroll 8
                for (int k = lane; k < H / 4; k += 32) {
                    float4 wv = __ldg(&wrow[k]);
                    float4 hv = h_s[k];
                    acc += wv.x * hv.x + wv.y * hv.y + wv.z * hv.z + wv.w * hv.w;
                }
                #pragma unroll
                for (int o = 16; o > 0; o >>= 1)
                    acc += __shfl_down_sync(0xffffffffu, acc, o);
                if (lane == 0) gsm[gate][jj] = acc;
            }
        }
        __syncthreads();

        // Elementwise LSTM cell update for this block's 16 indices
        if (tid < JPB) {
            const int   j  = j0 + tid;
            const float xt = x[t];
            float v[4];
            #pragma unroll
            for (int g = 0; g < 4; ++g) {
                const int row = g * H + j;
                const float dot = (t > 0) ? gsm[g][tid] : 0.0f;
                v[g] = fmaf(w_ih[row], xt, b_ih[row] + b_hh[row]) + dot;
            }
            const float ig = 1.0f / (1.0f + expf(-v[0]));
            const float fg = 1.0f / (1.0f + expf(-v[1]));
            const float gg = tanhf(v[2]);
            const float og = 1.0f / (1.0f + expf(-v[3]));
            const float c  = fg * c_s[tid] + ig * gg;
            c_s[tid] = c;
            g_h[t & 1][j] = og * tanhf(c);
            __threadfence();                 // publish h before barrier arrive
        }
        grid_barrier();                      // all blocks see h_t, gsm safe to reuse
    }

    // Dense epilogue: out = dense_w @ h_last + dense_b. Blocks 0..127, one row each.
    if (blockIdx.x < OUT) {
        const float* hw = g_h[(SEQ - 1) & 1];
        const float* wr = dense_w + (size_t)blockIdx.x * H;
        float acc = 0.0f;
        #pragma unroll
        for (int k = tid; k < H; k += NTHR)
            acc += wr[k] * hw[k];
        #pragma unroll
        for (int o = 16; o > 0; o >>= 1)
            acc += __shfl_down_sync(0xffffffffu, acc, o);
        if (lane == 0) red[wid] = acc;
        __syncthreads();
        if (tid == 0) {
            float s = 0.0f;
            #pragma unroll
            for (int w = 0; w < NTHR / 32; ++w) s += red[w];
            out[blockIdx.x] = s + dense_b[blockIdx.x];
        }
    }
}

extern "C" void kernel_launch(void* const* d_in, const int* in_sizes, int n_in,
                              void* d_out, int out_size) {
    const float* x       = (const float*)d_in[0];
    const float* w_ih    = (const float*)d_in[1];
    const float* w_hh    = (const float*)d_in[2];
    const float* b_ih    = (const float*)d_in[3];
    const float* b_hh    = (const float*)d_in[4];
    const float* dense_w = (const float*)d_in[5];
    const float* dense_b = (const float*)d_in[6];
    lstm_persistent_kernel<<<NBLK, NTHR>>>(x, w_ih, w_hh, b_ih, b_hh,
                                           dense_w, dense_b, (float*)d_out);
}

// round 3
// speedup vs baseline: 1.6634x; 1.6634x over previous
#include <cuda_runtime.h>
#include <math.h>

#define SEQ  40
#define H    4096
#define OUT  128
#define NBLK 256
#define NTHR 256
#define JPB  (H / NBLK)     // 16 hidden indices per block
#define ROWS (4 * H)        // 16384 gate rows
#define BLK32 256           // 32-byte blocks per row (16 int16 weights each)

// ---- persistent device state (no allocations allowed) ----
__device__ float    g_h[2][H];                                   // ping-pong hidden state
__device__ float    g_scale[ROWS];                               // per-row dequant scale
__device__ __align__(256) unsigned g_wq[(size_t)ROWS * (H / 2)]; // 134 MB biased-u16 weights
__device__ unsigned g_bar_count = 0;
__device__ unsigned g_bar_gen   = 0;

// ---------------- grid barrier ----------------
__device__ __forceinline__ void grid_barrier() {
    __syncthreads();
    if (threadIdx.x == 0) {
        unsigned gen = atomicAdd(&g_bar_gen, 0u);
        __threadfence();
        if (atomicAdd(&g_bar_count, 1u) == NBLK - 1u) {
            g_bar_count = 0;
            __threadfence();
            atomicAdd(&g_bar_gen, 1u);
        } else {
            volatile unsigned* vg = &g_bar_gen;
            while (*vg == gen) { }
            __threadfence();
        }
    }
    __syncthreads();
}

// ---------------- quantization prologue ----------------
// u16 = round(w * 32767/rowmax) + 32768, packed 2-per-u32, exact round via 2^23 magic.
__global__ __launch_bounds__(256) void quant_kernel(const float* __restrict__ w_hh) {
    const int warp = threadIdx.x >> 5, lane = threadIdx.x & 31;
    const int r = blockIdx.x * 8 + warp;
    const float4* row = (const float4*)(w_hh + (size_t)r * H);
    float mx = 0.0f;
    #pragma unroll 8
    for (int c = lane; c < H / 4; c += 32) {
        float4 v = __ldg(row + c);
        mx = fmaxf(mx, fmaxf(fmaxf(fabsf(v.x), fabsf(v.y)),
                             fmaxf(fabsf(v.z), fabsf(v.w))));
    }
    #pragma unroll
    for (int o = 16; o > 0; o >>= 1) mx = fmaxf(mx, __shfl_xor_sync(0xffffffffu, mx, o));
    const float inv = (mx > 0.0f) ? 32767.0f / mx : 0.0f;
    if (lane == 0) g_scale[r] = mx * (1.0f / 32767.0f);

    uint4* dst = (uint4*)g_wq + (size_t)r * (H / 8);
    #pragma unroll 4
    for (int c = lane; c < H / 8; c += 32) {
        float4 a = __ldg(row + 2 * c);
        float4 b = __ldg(row + 2 * c + 1);
        unsigned qa0 = __float_as_uint(fmaf(a.x, inv, 32768.0f) + 8388608.0f);
        unsigned qa1 = __float_as_uint(fmaf(a.y, inv, 32768.0f) + 8388608.0f);
        unsigned qa2 = __float_as_uint(fmaf(a.z, inv, 32768.0f) + 8388608.0f);
        unsigned qa3 = __float_as_uint(fmaf(a.w, inv, 32768.0f) + 8388608.0f);
        unsigned qb0 = __float_as_uint(fmaf(b.x, inv, 32768.0f) + 8388608.0f);
        unsigned qb1 = __float_as_uint(fmaf(b.y, inv, 32768.0f) + 8388608.0f);
        unsigned qb2 = __float_as_uint(fmaf(b.z, inv, 32768.0f) + 8388608.0f);
        unsigned qb3 = __float_as_uint(fmaf(b.w, inv, 32768.0f) + 8388608.0f);
        uint4 o;
        o.x = __byte_perm(qa0, qa1, 0x5410);
        o.y = __byte_perm(qa2, qa3, 0x5410);
        o.z = __byte_perm(qb0, qb1, 0x5410);
        o.w = __byte_perm(qb2, qb3, 0x5410);
        dst[c] = o;
    }
}

// ---------------- exact dequant (PRMT + FADD), then FFMA ----------------
__device__ __forceinline__ float dq_lo(unsigned p) {
    return __uint_as_float(__byte_perm(p, 0x4B000000u, 0x7410)) - 8421376.0f;
}
__device__ __forceinline__ float dq_hi(unsigned p) {
    return __uint_as_float(__byte_perm(p, 0x4B000000u, 0x7432)) - 8421376.0f;
}

// 256-bit weight load with L2 eviction hint (sm_103 requires v8.b32 for hints)
template <bool PROT>
__device__ __forceinline__ void ldw256(const unsigned* p, unsigned (&v)[8]) {
    if (PROT)
        asm volatile("ld.global.nc.L2::evict_last.v8.b32 {%0,%1,%2,%3,%4,%5,%6,%7}, [%8];"
                     : "=r"(v[0]), "=r"(v[1]), "=r"(v[2]), "=r"(v[3]),
                       "=r"(v[4]), "=r"(v[5]), "=r"(v[6]), "=r"(v[7]) : "l"(p));
    else
        asm volatile("ld.global.nc.L2::evict_first.v8.b32 {%0,%1,%2,%3,%4,%5,%6,%7}, [%8];"
                     : "=r"(v[0]), "=r"(v[1]), "=r"(v[2]), "=r"(v[3]),
                       "=r"(v[4]), "=r"(v[5]), "=r"(v[6]), "=r"(v[7]) : "l"(p));
}

// 8 rows per warp. 32B-block c covers h[16c..16c+15] = h_s[0..3][c].
template <bool PROT>
__device__ __forceinline__ void warp_rows(const float4 (&hs)[4][257],
                                          int wid, int lane, int j0,
                                          float (&gsm)[4][JPB]) {
    const unsigned* wp[8];
    int grow[8];
    #pragma unroll
    for (int rr = 0; rr < 8; ++rr) {
        int rloc = wid * 8 + rr;
        grow[rr] = (rloc >> 4) * H + j0 + (rloc & 15);
        wp[rr] = g_wq + (size_t)grow[rr] * (H / 2);
    }
    float acc[8];
    #pragma unroll
    for (int rr = 0; rr < 8; ++rr) acc[rr] = 0.0f;

    #pragma unroll
    for (int it = 0; it < BLK32 / 32; ++it) {
        const int c = it * 32 + lane;
        const float4 h0 = hs[0][c], h1 = hs[1][c], h2 = hs[2][c], h3 = hs[3][c];
        #pragma unroll
        for (int rr = 0; rr < 8; ++rr) {
            unsigned w[8];
            ldw256<PROT>(wp[rr] + c * 8, w);
            float s;
            s = dq_lo(w[0]) * h0.x;
            s = fmaf(dq_hi(w[0]), h0.y, s);
            s = fmaf(dq_lo(w[1]), h0.z, s);
            s = fmaf(dq_hi(w[1]), h0.w, s);
            s = fmaf(dq_lo(w[2]), h1.x, s);
            s = fmaf(dq_hi(w[2]), h1.y, s);
            s = fmaf(dq_lo(w[3]), h1.z, s);
            s = fmaf(dq_hi(w[3]), h1.w, s);
            s = fmaf(dq_lo(w[4]), h2.x, s);
            s = fmaf(dq_hi(w[4]), h2.y, s);
            s = fmaf(dq_lo(w[5]), h2.z, s);
            s = fmaf(dq_hi(w[5]), h2.w, s);
            s = fmaf(dq_lo(w[6]), h3.x, s);
            s = fmaf(dq_hi(w[6]), h3.y, s);
            s = fmaf(dq_lo(w[7]), h3.z, s);
            s = fmaf(dq_hi(w[7]), h3.w, s);
            acc[rr] += s;
        }
    }
    #pragma unroll
    for (int rr = 0; rr < 8; ++rr) {
        float a = acc[rr];
        #pragma unroll
        for (int o = 16; o > 0; o >>= 1) a += __shfl_down_sync(0xffffffffu, a, o);
        if (lane == 0) {
            int rloc = wid * 8 + rr;
            gsm[rloc >> 4][rloc & 15] = a * g_scale[grow[rr]];
        }
    }
}

// ---------------- persistent LSTM kernel ----------------
__global__ __launch_bounds__(NTHR, 2)
void lstm_persistent_kernel(const float* __restrict__ x,
                            const float* __restrict__ w_ih,
                            const float* __restrict__ b_ih,
                            const float* __restrict__ b_hh,
                            const float* __restrict__ dense_w,
                            const float* __restrict__ dense_b,
                            float* __restrict__ out) {
    __shared__ float4 h_s[4][257];     // de-interleaved h_{t-1}, padded: conflict-free
    __shared__ float  gsm[4][JPB];
    __shared__ float  c_s[JPB];
    __shared__ float  red[NTHR / 32];

    const int tid  = threadIdx.x;
    const int lane = tid & 31;
    const int wid  = tid >> 5;
    const int j0   = blockIdx.x * JPB;

    if (tid < JPB) c_s[tid] = 0.0f;

    for (int t = 0; t < SEQ; ++t) {
        if (t > 0) {
            const float4* hb = (const float4*)g_h[(t - 1) & 1];
            #pragma unroll
            for (int k = 0; k < (H / 4) / NTHR; ++k) {
                const int idx = tid + k * NTHR;        // 0..1023
                h_s[idx & 3][idx >> 2] = hb[idx];      // padded: conflict-free STS
            }
            __syncthreads();
            // warps 0..5 -> gates i,f,g: pin in L2. warps 6..7 -> gate o: stream.
            if (wid < 6) warp_rows<true>(h_s, wid, lane, j0, gsm);
            else         warp_rows<false>(h_s, wid, lane, j0, gsm);
        }
        __syncthreads();

        if (tid < JPB) {
            const int   j  = j0 + tid;
            const float xt = x[t];
            float v[4];
            #pragma unroll
            for (int g = 0; g < 4; ++g) {
                const int row = g * H + j;
                const float dot = (t > 0) ? gsm[g][tid] : 0.0f;
                v[g] = fmaf(w_ih[row], xt, b_ih[row] + b_hh[row]) + dot;
            }
            const float ig = 1.0f / (1.0f + expf(-v[0]));
            const float fg = 1.0f / (1.0f + expf(-v[1]));
            const float gg = tanhf(v[2]);
            const float og = 1.0f / (1.0f + expf(-v[3]));
            const float c  = fg * c_s[tid] + ig * gg;
            c_s[tid] = c;
            g_h[t & 1][j] = og * tanhf(c);
            __threadfence();
        }
        grid_barrier();
    }

    // Dense epilogue: blocks 0..127 each compute one output row (fp32).
    if (blockIdx.x < OUT) {
        const float* hw = g_h[(SEQ - 1) & 1];
        const float* wr = dense_w + (size_t)blockIdx.x * H;
        float acc = 0.0f;
        #pragma unroll
        for (int k = tid; k < H; k += NTHR)
            acc += wr[k] * hw[k];
        #pragma unroll
        for (int o = 16; o > 0; o >>= 1)
            acc += __shfl_down_sync(0xffffffffu, acc, o);
        if (lane == 0) red[wid] = acc;
        __syncthreads();
        if (tid == 0) {
            float s = 0.0f;
            #pragma unroll
            for (int w = 0; w < NTHR / 32; ++w) s += red[w];
            out[blockIdx.x] = s + dense_b[blockIdx.x];
        }
    }
}

extern "C" void kernel_launch(void* const* d_in, const int* in_sizes, int n_in,
                              void* d_out, int out_size) {
    const float* x       = (const float*)d_in[0];
    const float* w_ih    = (const float*)d_in[1];
    const float* w_hh    = (const float*)d_in[2];
    const float* b_ih    = (const float*)d_in[3];
    const float* b_hh    = (const float*)d_in[4];
    const float* dense_w = (const float*)d_in[5];
    const float* dense_b = (const float*)d_in[6];

    quant_kernel<<<ROWS / 8, 256>>>(w_hh);
    lstm_persistent_kernel<<<NBLK, NTHR>>>(x, w_ih, b_ih, b_hh,
                                           dense_w, dense_b, (float*)d_out);
}

// round 4
// speedup vs baseline: 3.0879x; 1.8564x over previous
#include <cuda_runtime.h>
#include <math.h>

#define SEQ  40
#define H    4096
#define OUT  128
#define NBLK 256
#define NTHR 256
#define JPB  (H / NBLK)     // 16 hidden indices per block
#define ROWS (4 * H)        // 16384 gate rows
#define RQ4  (H / 16)       // 256 uint4 (16 int8 weights) per row

typedef unsigned long long u64;

// ---- persistent device state (no allocations allowed) ----
__device__ float    g_h[2][H];                                  // ping-pong hidden state
__device__ float    g_scale[ROWS];                              // per-row dequant scale
__device__ __align__(256) unsigned g_wq[(size_t)ROWS * (H / 4)];// 67 MB biased-u8 weights
__device__ unsigned g_bar_count = 0;
__device__ unsigned g_bar_gen   = 0;

// ---------------- packed f32x2 helpers ----------------
__device__ __forceinline__ u64 pack64(unsigned lo, unsigned hi) {
    u64 r; asm("mov.b64 %0, {%1,%2};" : "=l"(r) : "r"(lo), "r"(hi)); return r;
}
__device__ __forceinline__ u64 packf2(float lo, float hi) {
    u64 r; asm("mov.b64 %0, {%1,%2};" : "=l"(r) : "f"(lo), "f"(hi)); return r;
}
__device__ __forceinline__ void unpackf2(u64 v, float& lo, float& hi) {
    asm("mov.b64 {%0,%1}, %2;" : "=f"(lo), "=f"(hi) : "l"(v));
}
__device__ __forceinline__ u64 addx2(u64 a, u64 b) {
    u64 r; asm("add.rn.f32x2 %0, %1, %2;" : "=l"(r) : "l"(a), "l"(b)); return r;
}
__device__ __forceinline__ u64 fmax2(u64 a, u64 b, u64 c) {
    u64 r; asm("fma.rn.f32x2 %0, %1, %2, %3;" : "=l"(r) : "l"(a), "l"(b), "l"(c)); return r;
}

// -8388736.0f = -(2^23 + 128) in both lanes (removes magic + bias exactly)
#define NEG_MAGIC 0xCB000080u

// ---------------- grid barrier ----------------
__device__ __forceinline__ void grid_barrier() {
    __syncthreads();
    if (threadIdx.x == 0) {
        unsigned gen = atomicAdd(&g_bar_gen, 0u);
        __threadfence();
        if (atomicAdd(&g_bar_count, 1u) == NBLK - 1u) {
            g_bar_count = 0;
            __threadfence();
            atomicAdd(&g_bar_gen, 1u);
        } else {
            volatile unsigned* vg = &g_bar_gen;
            while (*vg == gen) { }
            __threadfence();
        }
    }
    __syncthreads();
}

// ---------------- int8 quantization prologue ----------------
// b = round(w * 127/rowmax) + 128  (u8, exact RN via 2^23 magic), 16 per uint4.
__global__ __launch_bounds__(256) void quant_kernel(const float* __restrict__ w_hh) {
    const int warp = threadIdx.x >> 5, lane = threadIdx.x & 31;
    const int r = blockIdx.x * 8 + warp;
    const float4* row = (const float4*)(w_hh + (size_t)r * H);
    float mx = 0.0f;
    #pragma unroll 8
    for (int c = lane; c < H / 4; c += 32) {
        float4 v = __ldg(row + c);
        mx = fmaxf(mx, fmaxf(fmaxf(fabsf(v.x), fabsf(v.y)),
                             fmaxf(fabsf(v.z), fabsf(v.w))));
    }
    #pragma unroll
    for (int o = 16; o > 0; o >>= 1) mx = fmaxf(mx, __shfl_xor_sync(0xffffffffu, mx, o));
    const float inv = (mx > 0.0f) ? 127.0f / mx : 0.0f;
    if (lane == 0) g_scale[r] = mx * (1.0f / 127.0f);

    uint4* dst = (uint4*)g_wq + (size_t)r * RQ4;
    for (int c = lane; c < RQ4; c += 32) {
        unsigned m[16];
        #pragma unroll
        for (int q = 0; q < 4; ++q) {
            float4 v = __ldg(row + 4 * c + q);
            m[4 * q + 0] = __float_as_uint(fmaf(v.x, inv, 128.0f) + 8388608.0f);
            m[4 * q + 1] = __float_as_uint(fmaf(v.y, inv, 128.0f) + 8388608.0f);
            m[4 * q + 2] = __float_as_uint(fmaf(v.z, inv, 128.0f) + 8388608.0f);
            m[4 * q + 3] = __float_as_uint(fmaf(v.w, inv, 128.0f) + 8388608.0f);
        }
        uint4 o;
        #pragma unroll
        for (int q = 0; q < 4; ++q) {
            unsigned t0 = __byte_perm(m[4 * q + 0], m[4 * q + 1], 0x0040);
            unsigned t1 = __byte_perm(m[4 * q + 2], m[4 * q + 3], 0x0040);
            ((unsigned*)&o)[q] = __byte_perm(t0, t1, 0x5410);
        }
        dst[c] = o;
    }
}

// ---------------- per-warp matvec: 8 rows, int8 weights, f32x2 math ----------------
__device__ __forceinline__ void warp_rows(const float4 (&hs)[4][257],
                                          int wid, int lane, int j0,
                                          float (&gsm)[4][JPB]) {
    const uint4* wp[8];
    int grow[8];
    #pragma unroll
    for (int rr = 0; rr < 8; ++rr) {
        int rloc = wid * 8 + rr;
        grow[rr] = (rloc >> 4) * H + j0 + (rloc & 15);
        wp[rr] = (const uint4*)g_wq + (size_t)grow[rr] * RQ4;
    }
    u64 acc[8];
    #pragma unroll
    for (int rr = 0; rr < 8; ++rr) acc[rr] = 0ull;

    const u64 C2 = pack64(NEG_MAGIC, NEG_MAGIC);

    #pragma unroll
    for (int it = 0; it < RQ4 / 32; ++it) {        // 8 iterations
        const int c = it * 32 + lane;              // uint4 index; covers h[16c..16c+15]
        uint4 w[8];
        #pragma unroll
        for (int rr = 0; rr < 8; ++rr) w[rr] = __ldg(wp[rr] + c);

        const float4 h0 = hs[0][c], h1 = hs[1][c], h2 = hs[2][c], h3 = hs[3][c];
        const u64 hp0 = packf2(h0.x, h0.y), hp1 = packf2(h0.z, h0.w);
        const u64 hp2 = packf2(h1.x, h1.y), hp3 = packf2(h1.z, h1.w);
        const u64 hp4 = packf2(h2.x, h2.y), hp5 = packf2(h2.z, h2.w);
        const u64 hp6 = packf2(h3.x, h3.y), hp7 = packf2(h3.z, h3.w);
        const u64 hp[8] = {hp0, hp1, hp2, hp3, hp4, hp5, hp6, hp7};

        #pragma unroll
        for (int rr = 0; rr < 8; ++rr) {
            u64 a = acc[rr];
            #pragma unroll
            for (int q = 0; q < 4; ++q) {
                const unsigned v = ((const unsigned*)&w[rr])[q];
                const unsigned f0 = __byte_perm(v, 0x4B000000u, 0x7440);
                const unsigned f1 = __byte_perm(v, 0x4B000000u, 0x7441);
                const unsigned f2 = __byte_perm(v, 0x4B000000u, 0x7442);
                const unsigned f3 = __byte_perm(v, 0x4B000000u, 0x7443);
                a = fmax2(addx2(pack64(f0, f1), C2), hp[2 * q + 0], a);
                a = fmax2(addx2(pack64(f2, f3), C2), hp[2 * q + 1], a);
            }
            acc[rr] = a;
        }
    }
    #pragma unroll
    for (int rr = 0; rr < 8; ++rr) {
        float lo, hi;
        unpackf2(acc[rr], lo, hi);
        float a = lo + hi;
        #pragma unroll
        for (int o = 16; o > 0; o >>= 1) a += __shfl_down_sync(0xffffffffu, a, o);
        if (lane == 0) {
            int rloc = wid * 8 + rr;
            gsm[rloc >> 4][rloc & 15] = a * g_scale[grow[rr]];
        }
    }
}

// ---------------- persistent LSTM kernel ----------------
__global__ __launch_bounds__(NTHR, 2)
void lstm_persistent_kernel(const float* __restrict__ x,
                            const float* __restrict__ w_ih,
                            const float* __restrict__ b_ih,
                            const float* __restrict__ b_hh,
                            const float* __restrict__ dense_w,
                            const float* __restrict__ dense_b,
                            float* __restrict__ out) {
    __shared__ float4 h_s[4][257];     // de-interleaved h_{t-1}, padded (conflict-free)
    __shared__ float  gsm[4][JPB];
    __shared__ float  c_s[JPB];
    __shared__ float  red[NTHR / 32];

    const int tid  = threadIdx.x;
    const int lane = tid & 31;
    const int wid  = tid >> 5;
    const int j0   = blockIdx.x * JPB;

    if (tid < JPB) c_s[tid] = 0.0f;

    for (int t = 0; t < SEQ; ++t) {
        if (t > 0) {
            const float4* hb = (const float4*)g_h[(t - 1) & 1];
            #pragma unroll
            for (int k = 0; k < (H / 4) / NTHR; ++k) {
                const int idx = tid + k * NTHR;        // 0..1023
                h_s[idx & 3][idx >> 2] = hb[idx];
            }
            __syncthreads();
            warp_rows(h_s, wid, lane, j0, gsm);
        }
        __syncthreads();

        if (tid < JPB) {
            const int   j  = j0 + tid;
            const float xt = x[t];
            float v[4];
            #pragma unroll
            for (int g = 0; g < 4; ++g) {
                const int row = g * H + j;
                const float dot = (t > 0) ? gsm[g][tid] : 0.0f;
                v[g] = fmaf(w_ih[row], xt, b_ih[row] + b_hh[row]) + dot;
            }
            const float ig = 1.0f / (1.0f + expf(-v[0]));
            const float fg = 1.0f / (1.0f + expf(-v[1]));
            const float gg = tanhf(v[2]);
            const float og = 1.0f / (1.0f + expf(-v[3]));
            const float c  = fg * c_s[tid] + ig * gg;
            c_s[tid] = c;
            g_h[t & 1][j] = og * tanhf(c);
            __threadfence();
        }
        grid_barrier();
    }

    // Dense epilogue: blocks 0..127 each compute one output row (fp32).
    if (blockIdx.x < OUT) {
        const float* hw = g_h[(SEQ - 1) & 1];
        const float* wr = dense_w + (size_t)blockIdx.x * H;
        float acc = 0.0f;
        #pragma unroll
        for (int k = tid; k < H; k += NTHR)
            acc += wr[k] * hw[k];
        #pragma unroll
        for (int o = 16; o > 0; o >>= 1)
            acc += __shfl_down_sync(0xffffffffu, acc, o);
        if (lane == 0) red[wid] = acc;
        __syncthreads();
        if (tid == 0) {
            float s = 0.0f;
            #pragma unroll
            for (int w = 0; w < NTHR / 32; ++w) s += red[w];
            out[blockIdx.x] = s + dense_b[blockIdx.x];
        }
    }
}

extern "C" void kernel_launch(void* const* d_in, const int* in_sizes, int n_in,
                              void* d_out, int out_size) {
    const float* x       = (const float*)d_in[0];
    const float* w_ih    = (const float*)d_in[1];
    const float* w_hh    = (const float*)d_in[2];
    const float* b_ih    = (const float*)d_in[3];
    const float* b_hh    = (const float*)d_in[4];
    const float* dense_w = (const float*)d_in[5];
    const float* dense_b = (const float*)d_in[6];

    quant_kernel<<<ROWS / 8, 256>>>(w_hh);
    lstm_persistent_kernel<<<NBLK, NTHR>>>(x, w_ih, b_ih, b_hh,
                                           dense_w, dense_b, (float*)d_out);
}